// round 16
// baseline (speedup 1.0000x reference)
#include <cuda_runtime.h>
#include <cuda_fp16.h>
#include <cuda_bf16.h>
#include <mma.h>
#include <cstdint>
#include <cstddef>

using namespace nvcuda;

// ---------------- problem constants ----------------
// B=1, IMG=2048, REF=512, TXT=256, D=3072, H=24, hd=128
static constexpr int D_      = 3072;
static constexpr int L_      = 2816;
static constexpr int LX_     = 2304;
static constexpr int IMG_    = 2048;
static constexpr int NOUT_   = 21504;
static constexpr int CATN_   = 15360;
static constexpr int QKVW_   = 9216;

// ---------------- scratch (static device globals; no allocs) ----------------
__device__ float  g_mod[9216];
__device__ float  g_modpart[12 * 9216];
__device__ __half g_xm[L_ * D_];
__device__ __half g_refc[512 * D_];
__device__ __half g_rtmp[512 * D_];
__device__ __half g_h[(size_t)L_ * QKVW_];
__device__ __half g_q[24 * L_ * 128];
__device__ __half g_k[24 * L_ * 128];
__device__ __half g_v[24 * L_ * 128];
__device__ __half g_cat[(size_t)LX_ * CATN_];
__device__ __half g_w1h[(size_t)D_ * NOUT_];
__device__ __half g_w2h[(size_t)CATN_ * D_];
__device__ __half g_wr1h[D_ * D_];
__device__ __half g_wr2h[D_ * D_];

__device__ __forceinline__ float gelu_f(float x) {
    float x3 = x * x * x;
    return 0.5f * x * (1.0f + tanhf(0.7978845608028654f * (x + 0.044715f * x3)));
}

// -------- cp.async helpers --------
__device__ __forceinline__ void cp_async16(void* smem, const void* gmem) {
    uint32_t s = (uint32_t)__cvta_generic_to_shared(smem);
    asm volatile("cp.async.cg.shared.global [%0], [%1], 16;" :: "r"(s), "l"(gmem));
}
__device__ __forceinline__ void cp_commit() {
    asm volatile("cp.async.commit_group;");
}
template <int N>
__device__ __forceinline__ void cp_wait() {
    asm volatile("cp.async.wait_group %0;" :: "n"(N));
}

// ======================================================================
// weight convert: float -> half, 8 elems/thread
// ======================================================================
__global__ __launch_bounds__(256) void h_convert(const float* __restrict__ src,
                                                 __half* __restrict__ dst) {
    const size_t i = (size_t)blockIdx.x * 256 + threadIdx.x;
    float4 a = ((const float4*)src)[i * 2];
    float4 b = ((const float4*)src)[i * 2 + 1];
    __half2 h[4];
    h[0] = __floats2half2_rn(a.x, a.y);
    h[1] = __floats2half2_rn(a.z, a.w);
    h[2] = __floats2half2_rn(b.x, b.y);
    h[3] = __floats2half2_rn(b.z, b.w);
    ((uint4*)dst)[i] = *(uint4*)h;
}

// ======================================================================
// mod = silu(vec) @ mod_w + mod_b  (two-stage, deterministic, fp32)
// ======================================================================
__global__ __launch_bounds__(256) void mod_part_kernel(const float* __restrict__ vec,
                                                       const float* __restrict__ mw) {
    __shared__ float sv[256];
    const int i0 = blockIdx.y * 256;
    const int t = threadIdx.x;
    float v = vec[i0 + t];
    sv[t] = v / (1.0f + __expf(-v));
    __syncthreads();
    const int j = blockIdx.x * 256 + t;
    float acc = 0.0f;
#pragma unroll 8
    for (int i = 0; i < 256; i++) acc += sv[i] * mw[(size_t)(i0 + i) * 9216 + j];
    g_modpart[blockIdx.y * 9216 + j] = acc;
}

__global__ void mod_reduce_kernel(const float* __restrict__ mb) {
    const int j = blockIdx.x * 256 + threadIdx.x;
    float a = mb[j];
#pragma unroll
    for (int s = 0; s < 12; s++) a += g_modpart[s * 9216 + j];
    g_mod[j] = a;
}

// ======================================================================
// round-copy ref -> g_refc (half)
// ======================================================================
__global__ __launch_bounds__(256) void refcopy_kernel(const float* __restrict__ ref) {
    const size_t i = (size_t)blockIdx.x * 256 + threadIdx.x;
    float4 v = ((const float4*)ref)[i];
    __half2 h[2];
    h[0] = __floats2half2_rn(v.x, v.y);
    h[1] = __floats2half2_rn(v.z, v.w);
    ((uint2*)g_refc)[i] = *(uint2*)h;
}

// ======================================================================
// x_mod = LN(x) * (1 + scale) + shift  -> g_xm half
// ======================================================================
__global__ __launch_bounds__(256) void xmod_kernel(const float* __restrict__ x) {
    const int row = blockIdx.x;
    const float* xr = x + (size_t)row * D_;
    const int t = threadIdx.x;
    float lv[12];
    float s = 0.f, s2 = 0.f;
#pragma unroll
    for (int i = 0; i < 12; i++) {
        float v = xr[t + i * 256];
        lv[i] = v; s += v; s2 += v * v;
    }
#pragma unroll
    for (int o = 16; o; o >>= 1) {
        s  += __shfl_xor_sync(0xffffffffu, s, o);
        s2 += __shfl_xor_sync(0xffffffffu, s2, o);
    }
    __shared__ float red[16];
    const int wi = t >> 5;
    if ((t & 31) == 0) { red[wi] = s; red[8 + wi] = s2; }
    __syncthreads();
    float ts = 0.f, ts2 = 0.f;
#pragma unroll
    for (int i = 0; i < 8; i++) { ts += red[i]; ts2 += red[8 + i]; }
    float mu   = ts * (1.0f / 3072.0f);
    float var  = ts2 * (1.0f / 3072.0f) - mu * mu;
    float rstd = rsqrtf(var + 1e-6f);
    const int dst = row < IMG_ ? row : row + 512;
    __half* o = g_xm + (size_t)dst * D_;
#pragma unroll
    for (int i = 0; i < 12; i++) {
        int c = t + i * 256;
        o[c] = __float2half_rn((lv[i] - mu) * rstd * (1.0f + g_mod[3072 + c]) + g_mod[c]);
    }
}

// ======================================================================
// LN with gamma/beta, in place on g_xm rows 2048..2559 (half)
// ======================================================================
__global__ __launch_bounds__(256) void refln_kernel(const float* __restrict__ w,
                                                    const float* __restrict__ b) {
    const int row = 2048 + blockIdx.x;
    __half* xr = g_xm + (size_t)row * D_;
    const int t = threadIdx.x;
    float lv[12];
    float s = 0.f, s2 = 0.f;
#pragma unroll
    for (int i = 0; i < 12; i++) {
        float v = __half2float(xr[t + i * 256]);
        lv[i] = v; s += v; s2 += v * v;
    }
#pragma unroll
    for (int o = 16; o; o >>= 1) {
        s  += __shfl_xor_sync(0xffffffffu, s, o);
        s2 += __shfl_xor_sync(0xffffffffu, s2, o);
    }
    __shared__ float red[16];
    const int wi = t >> 5;
    if ((t & 31) == 0) { red[wi] = s; red[8 + wi] = s2; }
    __syncthreads();
    float ts = 0.f, ts2 = 0.f;
#pragma unroll
    for (int i = 0; i < 8; i++) { ts += red[i]; ts2 += red[8 + i]; }
    float mu   = ts * (1.0f / 3072.0f);
    float var  = ts2 * (1.0f / 3072.0f) - mu * mu;
    float rstd = rsqrtf(var + 1e-6f);
#pragma unroll
    for (int i = 0; i < 12; i++) {
        int c = t + i * 256;
        xr[c] = __float2half_rn((lv[i] - mu) * rstd * w[c] + b[c]);
    }
}

// ======================================================================
// FP16 WMMA GEMM v4: block 128x128, BK=64, 4 warps (2x2), warp tile 64x64.
// 3-stage cp.async ring, ONE __syncthreads per k-tile, grouped swizzle.
// 2 CTAs/SM (regs 165, smem 105KB).
// mode 0: bias -> half C.   mode 1: bias+gelu -> half C.
// mode 2: out(float) = xres + (acc+bias)*gate (N==3072)
// mode 3: lin1 split: qkv -> g_h half; mlp -> gelu -> g_cat half
// ======================================================================
static constexpr int G3_AS = 128 * 72 * 2;    // 18432
static constexpr int G3_BS = 64 * 136 * 2;    // 17408
static constexpr int G3_STAGE = G3_AS + G3_BS;              // 35840
static constexpr int GEMM_SMEM_BYTES = 3 * G3_STAGE;        // 107520

__global__ __launch_bounds__(128) void gemm_h(
    const __half* __restrict__ A, const __half* __restrict__ B,
    const float* __restrict__ bias, void* __restrict__ Cv,
    int N, int K, int tilesM, int tilesN, int mode,
    const float* __restrict__ xres) {
    extern __shared__ __align__(16) char smem_raw[];
    const int tid = threadIdx.x;
    const int w  = tid >> 5;
    const int wr = w >> 1;     // 0..1  (64 rows each)
    const int wc = w & 1;      // 0..1  (64 cols each)

    // grouped swizzle: GROUPM m-tiles per wave keep B hot in L2
    const int GROUPM = 8;
    const int pid = blockIdx.x;
    const int group_size = GROUPM * tilesN;
    const int group_id = pid / group_size;
    const int first_m = group_id * GROUPM;
    const int gsz = min(GROUPM, tilesM - first_m);
    const int in_group = pid % group_size;
    const int m0 = (first_m + (in_group % gsz)) * 128;
    const int n0 = (in_group / gsz) * 128;

    auto stageA = [&](int kt, int buf) {
        const int k0 = kt << 6;
        __half* dst = (__half*)(smem_raw + buf * G3_STAGE);
#pragma unroll
        for (int i = 0; i < 8; i++) {
            int idx = tid + (i << 7);          // 0..1023 chunks of 8 halfs
            int r = idx >> 3, c8 = (idx & 7) << 3;
            cp_async16(dst + r * 72 + c8, A + (size_t)(m0 + r) * K + k0 + c8);
        }
    };
    auto stageB = [&](int kt, int buf) {
        const int k0 = kt << 6;
        __half* dst = (__half*)(smem_raw + buf * G3_STAGE + G3_AS);
#pragma unroll
        for (int i = 0; i < 8; i++) {
            int idx = tid + (i << 7);          // 0..1023
            int r = idx >> 4, c8 = (idx & 15) << 3;
            cp_async16(dst + r * 136 + c8, B + (size_t)(k0 + r) * N + n0 + c8);
        }
    };

    wmma::fragment<wmma::accumulator, 16, 16, 16, float> acc[4][4];
#pragma unroll
    for (int i = 0; i < 4; i++)
#pragma unroll
        for (int j = 0; j < 4; j++) wmma::fill_fragment(acc[i][j], 0.0f);

    const int nk = K >> 6;
    stageA(0, 0); stageB(0, 0); cp_commit();
    stageA(1, 1); stageB(1, 1); cp_commit();

    int buf = 0;
    for (int kt = 0; kt < nk; kt++) {
        if (kt + 1 < nk) cp_wait<1>(); else cp_wait<0>();
        // one barrier per tile: also guarantees compute(kt-1) finished, making
        // its buffer ((kt+2)%3) safe to overwrite below.
        __syncthreads();
        if (kt + 2 < nk) {
            int nbuf = buf + 2; if (nbuf >= 3) nbuf -= 3;
            stageA(kt + 2, nbuf); stageB(kt + 2, nbuf); cp_commit();
        }
        __half* As = (__half*)(smem_raw + buf * G3_STAGE);
        __half* Bs = (__half*)(smem_raw + buf * G3_STAGE + G3_AS);
#pragma unroll
        for (int kk = 0; kk < 4; kk++) {
            wmma::fragment<wmma::matrix_a, 16, 16, 16, __half, wmma::row_major> af[4];
#pragma unroll
            for (int i = 0; i < 4; i++)
                wmma::load_matrix_sync(af[i], As + (wr * 64 + i * 16) * 72 + kk * 16, 72);
#pragma unroll
            for (int j = 0; j < 4; j++) {
                wmma::fragment<wmma::matrix_b, 16, 16, 16, __half, wmma::row_major> bf;
                wmma::load_matrix_sync(bf, Bs + (kk * 16) * 136 + wc * 64 + j * 16, 136);
#pragma unroll
                for (int i = 0; i < 4; i++)
                    wmma::mma_sync(acc[i][j], af[i], bf, acc[i][j]);
            }
        }
        if (++buf >= 3) buf = 0;
    }
    __syncthreads();   // all compute done before staging buffers are reused for C

    // staged epilogue: 128x136 float staging buffer (reuses pipeline smem)
    float* Cs = (float*)smem_raw;   // 69632 B <= 107520
#pragma unroll
    for (int i = 0; i < 4; i++)
#pragma unroll
        for (int j = 0; j < 4; j++)
            wmma::store_matrix_sync(Cs + (wr * 64 + i * 16) * 136 + wc * 64 + j * 16,
                                    acc[i][j], 136, wmma::mem_row_major);
    __syncthreads();
#pragma unroll 4
    for (int i = 0; i < 64; i++) {
        int e0 = (tid + (i << 7)) << 1;   // even elem idx within 128x128
        int r = e0 >> 7, c = e0 & 127;
        float v0 = Cs[r * 136 + c]     + bias[n0 + c];
        float v1 = Cs[r * 136 + c + 1] + bias[n0 + c + 1];
        const int gr = m0 + r, gc = n0 + c;
        if (mode == 0) {
            *(__half2*)((__half*)Cv + (size_t)gr * N + gc) = __floats2half2_rn(v0, v1);
        } else if (mode == 1) {
            *(__half2*)((__half*)Cv + (size_t)gr * N + gc) =
                __floats2half2_rn(gelu_f(v0), gelu_f(v1));
        } else if (mode == 2) {
            float* out = (float*)Cv;
            const float2 xv = *(const float2*)(xres + (size_t)gr * 3072 + gc);
            float2 o;
            o.x = xv.x + v0 * g_mod[6144 + gc];
            o.y = xv.y + v1 * g_mod[6144 + gc + 1];
            *(float2*)(out + (size_t)gr * 3072 + gc) = o;
        } else {  // mode 3
            if (n0 < QKVW_) {
                *(__half2*)((__half*)Cv + (size_t)gr * QKVW_ + gc) = __floats2half2_rn(v0, v1);
            } else if (gr < 2048 || gr >= 2560) {
                const int cr = gr < 2048 ? gr : gr - 512;
                *(__half2*)(g_cat + (size_t)cr * CATN_ + 3072 + (gc - QKVW_)) =
                    __floats2half2_rn(gelu_f(v0), gelu_f(v1));
            }
        }
    }
}

// ======================================================================
// QKV postprocess v2: one warp per head, pure shfl, lane-local RoPE.
// ======================================================================
__global__ __launch_bounds__(768) void qkv_kernel(const float* __restrict__ fcos,
                                                  const float* __restrict__ fsin,
                                                  const float* __restrict__ qw,
                                                  const float* __restrict__ kw) {
    const int l    = blockIdx.x;
    const int hh   = threadIdx.x >> 5;      // 0..23 (head)
    const int lane = threadIdx.x & 31;
    const __half* hr = g_h + (size_t)l * QKVW_ + hh * 128 + lane * 4;

    uint2 qa = *(const uint2*)hr;
    uint2 ka = *(const uint2*)(hr + 3072);
    uint2 va = *(const uint2*)(hr + 6144);
    __half2 qh0 = *(__half2*)&qa.x, qh1 = *(__half2*)&qa.y;
    __half2 kh0 = *(__half2*)&ka.x, kh1 = *(__half2*)&ka.y;
    float q0 = __half2float(__low2half(qh0)), q1 = __half2float(__high2half(qh0));
    float q2 = __half2float(__low2half(qh1)), q3 = __half2float(__high2half(qh1));
    float k0 = __half2float(__low2half(kh0)), k1 = __half2float(__high2half(kh0));
    float k2 = __half2float(__low2half(kh1)), k3 = __half2float(__high2half(kh1));

    float sq = q0 * q0 + q1 * q1 + q2 * q2 + q3 * q3;
    float sk = k0 * k0 + k1 * k1 + k2 * k2 + k3 * k3;
#pragma unroll
    for (int o = 16; o; o >>= 1) {
        sq += __shfl_xor_sync(0xffffffffu, sq, o);
        sk += __shfl_xor_sync(0xffffffffu, sk, o);
    }
    const float rq = rsqrtf(sq * (1.0f / 128.0f) + 1e-6f);
    const float rk = rsqrtf(sk * (1.0f / 128.0f) + 1e-6f);
    const float4 wq = *(const float4*)(qw + lane * 4);
    const float4 wk = *(const float4*)(kw + lane * 4);
    q0 *= rq * wq.x; q1 *= rq * wq.y; q2 *= rq * wq.z; q3 *= rq * wq.w;
    k0 *= rk * wk.x; k1 *= rk * wk.y; k2 *= rk * wk.z; k3 *= rk * wk.w;

    if (l < IMG_) {
        const int p = lane * 2;
        const float c0 = fcos[l * 64 + p],     s0 = fsin[l * 64 + p];
        const float c1 = fcos[l * 64 + p + 1], s1 = fsin[l * 64 + p + 1];
        float t;
        t  = q0 * c0 - q1 * s0;  q1 = q0 * s0 + q1 * c0;  q0 = t;
        t  = q2 * c1 - q3 * s1;  q3 = q2 * s1 + q3 * c1;  q2 = t;
        t  = k0 * c0 - k1 * s0;  k1 = k0 * s0 + k1 * c0;  k0 = t;
        t  = k2 * c1 - k3 * s1;  k3 = k2 * s1 + k3 * c1;  k2 = t;
    }
    const size_t base = ((size_t)hh * L_ + l) * 128 + lane * 4;
    __half2 o0 = __floats2half2_rn(q0, q1), o1 = __floats2half2_rn(q2, q3);
    uint2 pk;
    pk.x = *(uint32_t*)&o0; pk.y = *(uint32_t*)&o1;
    *(uint2*)(g_q + base) = pk;
    o0 = __floats2half2_rn(k0, k1); o1 = __floats2half2_rn(k2, k3);
    pk.x = *(uint32_t*)&o0; pk.y = *(uint32_t*)&o1;
    *(uint2*)(g_k + base) = pk;
    *(uint2*)(g_v + base) = va;
}

// ======================================================================
// Flash attention v2: 128-query tiles (fp16 tiles, fp32 softmax/accum).
// Grid (18, 24); img tiles 0-15, txt tiles 20-21 (ref-query tiles skipped).
// ======================================================================
static constexpr int FLASH_SMEM_BYTES = 230912;

__global__ __launch_bounds__(256) void flash_kernel() {
    extern __shared__ __align__(16) char smem_raw[];
    __half* Qs   = (__half*)smem_raw;
    __half* Ksb[2] = { (__half*)(smem_raw + 34816), (__half*)(smem_raw + 52224) };
    __half* Vsb[2] = { (__half*)(smem_raw + 69632), (__half*)(smem_raw + 87040) };
    float*  Os   = (float*)(smem_raw + 104448);
    float*  Sf   = (float*)(smem_raw + 174080);
    __half* Ph   = (__half*)(smem_raw + 210944);
    float*  m_s  = (float*)(smem_raw + 229376);
    float*  l_s  = (float*)(smem_raw + 229888);
    float*  a_s  = (float*)(smem_raw + 230400);

    const int hh = blockIdx.y;
    const int bq = blockIdx.x;              // 0..17
    const int qt = bq < 16 ? bq : bq + 4;   // skip ref-query tiles (16..19)
    const int t = threadIdx.x;
    const int w = t >> 5;
    const int wr = w >> 1;                  // 0..3 (32 rows each)
    const int wc = w & 1;                   // 0..1

    auto stageKV = [&](int kb, int buf) {
        const __half* Kg = g_k + ((size_t)hh * L_ + kb * 64) * 128;
        const __half* Vg = g_v + ((size_t)hh * L_ + kb * 64) * 128;
        __half* Kd = Ksb[buf];
        __half* Vd = Vsb[buf];
#pragma unroll
        for (int i = 0; i < 4; i++) {
            int idx = t + (i << 8);          // 0..1023 chunks of 8 halfs
            int r = idx >> 4, c8 = (idx & 15) << 3;
            cp_async16(Kd + r * 136 + c8, Kg + r * 128 + c8);
            cp_async16(Vd + r * 136 + c8, Vg + r * 128 + c8);
        }
    };

    // Q tile 128x128
    const __half* Qg = g_q + ((size_t)hh * L_ + qt * 128) * 128;
#pragma unroll
    for (int i = 0; i < 8; i++) {
        int idx = t + (i << 8);              // 0..2047
        int r = idx >> 4, c8 = (idx & 15) << 3;
        *(uint4*)(Qs + r * 136 + c8) = *(const uint4*)(Qg + r * 128 + c8);
    }
    for (int i = t; i < 17408; i += 256) Os[i] = 0.0f;
    if (t < 128) { m_s[t] = -1e30f; l_s[t] = 0.0f; }

    stageKV(0, 0); cp_commit();

    for (int kb = 0; kb < 44; kb++) {
        const int buf = kb & 1;
        if (kb + 1 < 44) {
            stageKV(kb + 1, buf ^ 1); cp_commit();
            cp_wait<1>();
        } else {
            cp_wait<0>();
        }
        __syncthreads();
        __half* Ks = Ksb[buf];
        __half* Vs = Vsb[buf];
        // ---- S = scale * Q @ K^T  (128x64, k=128); warp tile 32x32 ----
        {
            wmma::fragment<wmma::accumulator, 16, 16, 16, float> sacc[2][2];
#pragma unroll
            for (int i = 0; i < 2; i++)
#pragma unroll
                for (int j = 0; j < 2; j++) wmma::fill_fragment(sacc[i][j], 0.0f);
#pragma unroll
            for (int kk = 0; kk < 8; kk++) {
                wmma::fragment<wmma::matrix_a, 16, 16, 16, __half, wmma::row_major> af[2];
#pragma unroll
                for (int i = 0; i < 2; i++)
                    wmma::load_matrix_sync(af[i], Qs + (wr * 32 + i * 16) * 136 + kk * 16, 136);
#pragma unroll
                for (int j = 0; j < 2; j++) {
                    wmma::fragment<wmma::matrix_b, 16, 16, 16, __half, wmma::col_major> bf;
                    wmma::load_matrix_sync(bf, Ks + (wc * 32 + j * 16) * 136 + kk * 16, 136);
#pragma unroll
                    for (int i = 0; i < 2; i++)
                        wmma::mma_sync(sacc[i][j], af[i], bf, sacc[i][j]);
                }
            }
            const float scl = 0.088388347648318447f;  // 1/sqrt(128)
#pragma unroll
            for (int i = 0; i < 2; i++)
#pragma unroll
                for (int j = 0; j < 2; j++) {
#pragma unroll
                    for (int e = 0; e < sacc[i][j].num_elements; e++) sacc[i][j].x[e] *= scl;
                    wmma::store_matrix_sync(Sf + (wr * 32 + i * 16) * 72 + wc * 32 + j * 16,
                                            sacc[i][j], 72, wmma::mem_row_major);
                }
        }
        __syncthreads();
        // ---- streaming softmax: 2 threads per row; P -> half ----
        {
            const int r = t >> 1, l2 = t & 1;
            float* srow = Sf + r * 72;
            __half* prow = Ph + r * 72;
            float mx = -1e30f;
#pragma unroll
            for (int c = l2; c < 64; c += 2) mx = fmaxf(mx, srow[c]);
            mx = fmaxf(mx, __shfl_xor_sync(0xffffffffu, mx, 1));
            float mold = m_s[r];
            float mnew = fmaxf(mold, mx);
            float sum = 0.0f;
#pragma unroll
            for (int c = l2; c < 64; c += 2) {
                float p = __expf(srow[c] - mnew);
                prow[c] = __float2half_rn(p);
                sum += p;
            }
            sum += __shfl_xor_sync(0xffffffffu, sum, 1);
            if (l2 == 0) {
                float alpha = __expf(mold - mnew);
                a_s[r] = alpha;
                l_s[r] = l_s[r] * alpha + sum;
                m_s[r] = mnew;
            }
        }
        __syncthreads();
        // ---- rescale O accumulator (128x128) ----
#pragma unroll
        for (int i = 0; i < 64; i++) {
            int idx = t + (i << 8);
            int r = idx >> 7, c = idx & 127;
            Os[r * 136 + c] *= a_s[r];
        }
        __syncthreads();
        // ---- O += P @ V  (128x128, k=64); warp tile 32x64 ----
        {
            wmma::fragment<wmma::accumulator, 16, 16, 16, float> of[2][4];
#pragma unroll
            for (int i = 0; i < 2; i++)
#pragma unroll
                for (int j = 0; j < 4; j++)
                    wmma::load_matrix_sync(of[i][j],
                        Os + (wr * 32 + i * 16) * 136 + wc * 64 + j * 16,
                        136, wmma::mem_row_major);
#pragma unroll
            for (int kk = 0; kk < 4; kk++) {
                wmma::fragment<wmma::matrix_a, 16, 16, 16, __half, wmma::row_major> pf[2];
#pragma unroll
                for (int i = 0; i < 2; i++)
                    wmma::load_matrix_sync(pf[i], Ph + (wr * 32 + i * 16) * 72 + kk * 16, 72);
#pragma unroll
                for (int j = 0; j < 4; j++) {
                    wmma::fragment<wmma::matrix_b, 16, 16, 16, __half, wmma::row_major> vf;
                    wmma::load_matrix_sync(vf, Vs + (kk * 16) * 136 + wc * 64 + j * 16, 136);
#pragma unroll
                    for (int i = 0; i < 2; i++)
                        wmma::mma_sync(of[i][j], pf[i], vf, of[i][j]);
                }
            }
#pragma unroll
            for (int i = 0; i < 2; i++)
#pragma unroll
                for (int j = 0; j < 4; j++)
                    wmma::store_matrix_sync(Os + (wr * 32 + i * 16) * 136 + wc * 64 + j * 16,
                                            of[i][j], 136, wmma::mem_row_major);
        }
        __syncthreads();
    }
    // finalize: divide by l, write half into concat buffer (ref rows dropped)
    const int l0 = qt * 128;
#pragma unroll
    for (int i = 0; i < 64; i++) {
        int idx = t + (i << 8);
        int r = idx >> 7, c = idx & 127;
        const int l = l0 + r;
        const int cr = l < IMG_ ? l : l - 512;
        g_cat[(size_t)cr * CATN_ + hh * 128 + c] = __float2half_rn(Os[r * 136 + c] / l_s[r]);
    }
}

// ======================================================================
// host launcher  (GEMM kept at launch slot 4 for the ncu capture window)
// ======================================================================
extern "C" void kernel_launch(void* const* d_in, const int* in_sizes, int n_in,
                              void* d_out, int out_size) {
    const float* x    = (const float*)d_in[0];
    const float* vec  = (const float*)d_in[1];
    const float* ref  = (const float*)d_in[2];
    const float* fcos = (const float*)d_in[3];
    const float* fsin = (const float*)d_in[4];
    const float* modw = (const float*)d_in[5];
    const float* modb = (const float*)d_in[6];
    const float* rf1w = (const float*)d_in[7];
    const float* rf1b = (const float*)d_in[8];
    const float* rf2w = (const float*)d_in[9];
    const float* rf2b = (const float*)d_in[10];
    const float* rnw  = (const float*)d_in[11];
    const float* rnb  = (const float*)d_in[12];
    const float* l1w  = (const float*)d_in[13];
    const float* l1b  = (const float*)d_in[14];
    const float* l2w  = (const float*)d_in[15];
    const float* l2b  = (const float*)d_in[16];
    const float* qw   = (const float*)d_in[17];
    const float* kw   = (const float*)d_in[18];
    float* out = (float*)d_out;
    (void)in_sizes; (void)n_in; (void)out_size;

    cudaFuncSetAttribute(gemm_h, cudaFuncAttributeMaxDynamicSharedMemorySize, GEMM_SMEM_BYTES);
    cudaFuncSetAttribute(flash_kernel, cudaFuncAttributeMaxDynamicSharedMemorySize, FLASH_SMEM_BYTES);

    __half *xm_p, *refc_p, *rtmp_p, *h_p, *cat_p, *w1h_p, *w2h_p, *wr1h_p, *wr2h_p;
    cudaGetSymbolAddress((void**)&xm_p,   g_xm);
    cudaGetSymbolAddress((void**)&refc_p, g_refc);
    cudaGetSymbolAddress((void**)&rtmp_p, g_rtmp);
    cudaGetSymbolAddress((void**)&h_p,    g_h);
    cudaGetSymbolAddress((void**)&cat_p,  g_cat);
    cudaGetSymbolAddress((void**)&w1h_p,  g_w1h);
    cudaGetSymbolAddress((void**)&w2h_p,  g_w2h);
    cudaGetSymbolAddress((void**)&wr1h_p, g_wr1h);
    cudaGetSymbolAddress((void**)&wr2h_p, g_wr2h);

    // 1-3) ref copy + ref-weight converts
    refcopy_kernel<<<512 * 3072 / 1024, 256>>>(ref);
    h_convert<<<D_ * D_ / 2048, 256>>>(rf1w, wr1h_p);
    h_convert<<<D_ * D_ / 2048, 256>>>(rf2w, wr2h_p);
    // 4) ref MLP fc1  (profile-slot target)
    gemm_h<<<4 * 24, 128, GEMM_SMEM_BYTES>>>(refc_p, wr1h_p, rf1b, rtmp_p,
                                             D_, D_, 4, 24, 1, nullptr);
    // 5-7) modulation + LN/modulate
    mod_part_kernel<<<dim3(36, 12), 256>>>(vec, modw);
    mod_reduce_kernel<<<36, 256>>>(modb);
    xmod_kernel<<<LX_, 256>>>(x);
    // 8-9) ref MLP fc2 + LN -> xm rows 2048..2559
    gemm_h<<<4 * 24, 128, GEMM_SMEM_BYTES>>>(rtmp_p, wr2h_p, rf2b,
                                             xm_p + (size_t)2048 * D_,
                                             D_, D_, 4, 24, 0, nullptr);
    refln_kernel<<<512, 256>>>(rnw, rnb);
    // 10-11) lin1 weights + lin1 (split epilogue)
    h_convert<<<(int)((size_t)D_ * NOUT_ / 2048), 256>>>(l1w, w1h_p);
    gemm_h<<<22 * 168, 128, GEMM_SMEM_BYTES>>>(xm_p, w1h_p, l1b, h_p,
                                               NOUT_, D_, 22, 168, 3, nullptr);
    // 12) qkv split + rms + rope (one warp per head)
    qkv_kernel<<<L_, 768>>>(fcos, fsin, qw, kw);
    // 13-14) lin2 weights + attention
    h_convert<<<(int)((size_t)CATN_ * D_ / 2048), 256>>>(l2w, w2h_p);
    flash_kernel<<<dim3(18, 24), 256, FLASH_SMEM_BYTES>>>();
    // 15) lin2 with fused residual+gate epilogue -> d_out
    gemm_h<<<18 * 24, 128, GEMM_SMEM_BYTES>>>(cat_p, w2h_p, l2b, out,
                                              D_, CATN_, 18, 24, 2, x);
}

// round 17
// speedup vs baseline: 1.2835x; 1.2835x over previous
#include <cuda_runtime.h>
#include <cuda_fp16.h>
#include <cuda_bf16.h>
#include <mma.h>
#include <cstdint>
#include <cstddef>

using namespace nvcuda;

// ---------------- problem constants ----------------
static constexpr int D_      = 3072;
static constexpr int L_      = 2816;
static constexpr int LX_     = 2304;
static constexpr int IMG_    = 2048;
static constexpr int NOUT_   = 21504;
static constexpr int CATN_   = 15360;
static constexpr int QKVW_   = 9216;

// ---------------- scratch (static device globals; no allocs) ----------------
__device__ float  g_mod[9216];
__device__ float  g_modpart[12 * 9216];
__device__ __half g_xm[L_ * D_];
__device__ __half g_refc[512 * D_];
__device__ __half g_rtmp[512 * D_];
__device__ __half g_h[(size_t)L_ * QKVW_];
__device__ __half g_q[24 * L_ * 128];
__device__ __half g_k[24 * L_ * 128];
__device__ __half g_v[24 * L_ * 128];
__device__ __half g_cat[(size_t)LX_ * CATN_];
__device__ __half g_w1h[(size_t)D_ * NOUT_];
__device__ __half g_w2h[(size_t)CATN_ * D_];
__device__ __half g_wr1h[D_ * D_];
__device__ __half g_wr2h[D_ * D_];

__device__ __forceinline__ float gelu_f(float x) {
    float x3 = x * x * x;
    return 0.5f * x * (1.0f + tanhf(0.7978845608028654f * (x + 0.044715f * x3)));
}

// -------- cp.async helpers --------
__device__ __forceinline__ void cp_async16(void* smem, const void* gmem) {
    uint32_t s = (uint32_t)__cvta_generic_to_shared(smem);
    asm volatile("cp.async.cg.shared.global [%0], [%1], 16;" :: "r"(s), "l"(gmem));
}
__device__ __forceinline__ void cp_commit() {
    asm volatile("cp.async.commit_group;");
}
template <int N>
__device__ __forceinline__ void cp_wait() {
    asm volatile("cp.async.wait_group %0;" :: "n"(N));
}

// -------- ldmatrix / mma helpers --------
__device__ __forceinline__ void ldsm_x4(uint32_t& r0, uint32_t& r1, uint32_t& r2,
                                        uint32_t& r3, uint32_t addr) {
    asm volatile("ldmatrix.sync.aligned.m8n8.x4.shared.b16 {%0,%1,%2,%3}, [%4];"
                 : "=r"(r0), "=r"(r1), "=r"(r2), "=r"(r3) : "r"(addr));
}
__device__ __forceinline__ void ldsm_x4_trans(uint32_t& r0, uint32_t& r1, uint32_t& r2,
                                              uint32_t& r3, uint32_t addr) {
    asm volatile("ldmatrix.sync.aligned.m8n8.x4.trans.shared.b16 {%0,%1,%2,%3}, [%4];"
                 : "=r"(r0), "=r"(r1), "=r"(r2), "=r"(r3) : "r"(addr));
}
__device__ __forceinline__ void mma16816(float* c, const uint32_t* a,
                                         uint32_t b0, uint32_t b1) {
    asm volatile("mma.sync.aligned.m16n8k16.row.col.f32.f16.f16.f32 "
                 "{%0,%1,%2,%3}, {%4,%5,%6,%7}, {%8,%9}, {%0,%1,%2,%3};"
                 : "+f"(c[0]), "+f"(c[1]), "+f"(c[2]), "+f"(c[3])
                 : "r"(a[0]), "r"(a[1]), "r"(a[2]), "r"(a[3]), "r"(b0), "r"(b1));
}

// ======================================================================
// weight convert / mod / refcopy / xmod / refln  (unchanged)
// ======================================================================
__global__ __launch_bounds__(256) void h_convert(const float* __restrict__ src,
                                                 __half* __restrict__ dst) {
    const size_t i = (size_t)blockIdx.x * 256 + threadIdx.x;
    float4 a = ((const float4*)src)[i * 2];
    float4 b = ((const float4*)src)[i * 2 + 1];
    __half2 h[4];
    h[0] = __floats2half2_rn(a.x, a.y);
    h[1] = __floats2half2_rn(a.z, a.w);
    h[2] = __floats2half2_rn(b.x, b.y);
    h[3] = __floats2half2_rn(b.z, b.w);
    ((uint4*)dst)[i] = *(uint4*)h;
}

__global__ __launch_bounds__(256) void mod_part_kernel(const float* __restrict__ vec,
                                                       const float* __restrict__ mw) {
    __shared__ float sv[256];
    const int i0 = blockIdx.y * 256;
    const int t = threadIdx.x;
    float v = vec[i0 + t];
    sv[t] = v / (1.0f + __expf(-v));
    __syncthreads();
    const int j = blockIdx.x * 256 + t;
    float acc = 0.0f;
#pragma unroll 8
    for (int i = 0; i < 256; i++) acc += sv[i] * mw[(size_t)(i0 + i) * 9216 + j];
    g_modpart[blockIdx.y * 9216 + j] = acc;
}

__global__ void mod_reduce_kernel(const float* __restrict__ mb) {
    const int j = blockIdx.x * 256 + threadIdx.x;
    float a = mb[j];
#pragma unroll
    for (int s = 0; s < 12; s++) a += g_modpart[s * 9216 + j];
    g_mod[j] = a;
}

__global__ __launch_bounds__(256) void refcopy_kernel(const float* __restrict__ ref) {
    const size_t i = (size_t)blockIdx.x * 256 + threadIdx.x;
    float4 v = ((const float4*)ref)[i];
    __half2 h[2];
    h[0] = __floats2half2_rn(v.x, v.y);
    h[1] = __floats2half2_rn(v.z, v.w);
    ((uint2*)g_refc)[i] = *(uint2*)h;
}

__global__ __launch_bounds__(256) void xmod_kernel(const float* __restrict__ x) {
    const int row = blockIdx.x;
    const float* xr = x + (size_t)row * D_;
    const int t = threadIdx.x;
    float lv[12];
    float s = 0.f, s2 = 0.f;
#pragma unroll
    for (int i = 0; i < 12; i++) {
        float v = xr[t + i * 256];
        lv[i] = v; s += v; s2 += v * v;
    }
#pragma unroll
    for (int o = 16; o; o >>= 1) {
        s  += __shfl_xor_sync(0xffffffffu, s, o);
        s2 += __shfl_xor_sync(0xffffffffu, s2, o);
    }
    __shared__ float red[16];
    const int wi = t >> 5;
    if ((t & 31) == 0) { red[wi] = s; red[8 + wi] = s2; }
    __syncthreads();
    float ts = 0.f, ts2 = 0.f;
#pragma unroll
    for (int i = 0; i < 8; i++) { ts += red[i]; ts2 += red[8 + i]; }
    float mu   = ts * (1.0f / 3072.0f);
    float var  = ts2 * (1.0f / 3072.0f) - mu * mu;
    float rstd = rsqrtf(var + 1e-6f);
    const int dst = row < IMG_ ? row : row + 512;
    __half* o = g_xm + (size_t)dst * D_;
#pragma unroll
    for (int i = 0; i < 12; i++) {
        int c = t + i * 256;
        o[c] = __float2half_rn((lv[i] - mu) * rstd * (1.0f + g_mod[3072 + c]) + g_mod[c]);
    }
}

__global__ __launch_bounds__(256) void refln_kernel(const float* __restrict__ w,
                                                    const float* __restrict__ b) {
    const int row = 2048 + blockIdx.x;
    __half* xr = g_xm + (size_t)row * D_;
    const int t = threadIdx.x;
    float lv[12];
    float s = 0.f, s2 = 0.f;
#pragma unroll
    for (int i = 0; i < 12; i++) {
        float v = __half2float(xr[t + i * 256]);
        lv[i] = v; s += v; s2 += v * v;
    }
#pragma unroll
    for (int o = 16; o; o >>= 1) {
        s  += __shfl_xor_sync(0xffffffffu, s, o);
        s2 += __shfl_xor_sync(0xffffffffu, s2, o);
    }
    __shared__ float red[16];
    const int wi = t >> 5;
    if ((t & 31) == 0) { red[wi] = s; red[8 + wi] = s2; }
    __syncthreads();
    float ts = 0.f, ts2 = 0.f;
#pragma unroll
    for (int i = 0; i < 8; i++) { ts += red[i]; ts2 += red[8 + i]; }
    float mu   = ts * (1.0f / 3072.0f);
    float var  = ts2 * (1.0f / 3072.0f) - mu * mu;
    float rstd = rsqrtf(var + 1e-6f);
#pragma unroll
    for (int i = 0; i < 12; i++) {
        int c = t + i * 256;
        xr[c] = __float2half_rn((lv[i] - mu) * rstd * w[c] + b[c]);
    }
}

// ======================================================================
// FP16 WMMA GEMM (exact R14 config: 128x128, BK=64, 4 warps, 2-stage,
// two barriers per k-tile — best measured variant).
// ======================================================================
static constexpr int G3_AS = 128 * 72 * 2;    // 18432
static constexpr int G3_BS = 64 * 136 * 2;    // 17408
static constexpr int G3_STAGE = G3_AS + G3_BS;              // 35840
static constexpr int GEMM_SMEM_BYTES = 2 * G3_STAGE;        // 71680

__global__ __launch_bounds__(128) void gemm_h(
    const __half* __restrict__ A, const __half* __restrict__ B,
    const float* __restrict__ bias, void* __restrict__ Cv,
    int N, int K, int tilesM, int tilesN, int mode,
    const float* __restrict__ xres) {
    extern __shared__ __align__(16) char smem_raw[];
    const int tid = threadIdx.x;
    const int w  = tid >> 5;
    const int wr = w >> 1;
    const int wc = w & 1;

    const int GROUPM = 8;
    const int pid = blockIdx.x;
    const int group_size = GROUPM * tilesN;
    const int group_id = pid / group_size;
    const int first_m = group_id * GROUPM;
    const int gsz = min(GROUPM, tilesM - first_m);
    const int in_group = pid % group_size;
    const int m0 = (first_m + (in_group % gsz)) * 128;
    const int n0 = (in_group / gsz) * 128;

    auto stageA = [&](int kt, int buf) {
        const int k0 = kt << 6;
        __half* dst = (__half*)(smem_raw + buf * G3_STAGE);
#pragma unroll
        for (int i = 0; i < 8; i++) {
            int idx = tid + (i << 7);
            int r = idx >> 3, c8 = (idx & 7) << 3;
            cp_async16(dst + r * 72 + c8, A + (size_t)(m0 + r) * K + k0 + c8);
        }
    };
    auto stageB = [&](int kt, int buf) {
        const int k0 = kt << 6;
        __half* dst = (__half*)(smem_raw + buf * G3_STAGE + G3_AS);
#pragma unroll
        for (int i = 0; i < 8; i++) {
            int idx = tid + (i << 7);
            int r = idx >> 4, c8 = (idx & 15) << 3;
            cp_async16(dst + r * 136 + c8, B + (size_t)(k0 + r) * N + n0 + c8);
        }
    };

    wmma::fragment<wmma::accumulator, 16, 16, 16, float> acc[4][4];
#pragma unroll
    for (int i = 0; i < 4; i++)
#pragma unroll
        for (int j = 0; j < 4; j++) wmma::fill_fragment(acc[i][j], 0.0f);

    const int nk = K >> 6;
    stageA(0, 0); stageB(0, 0); cp_commit();

    for (int kt = 0; kt < nk; kt++) {
        const int buf = kt & 1;
        if (kt + 1 < nk) {
            stageA(kt + 1, buf ^ 1); stageB(kt + 1, buf ^ 1); cp_commit();
            cp_wait<1>();
        } else {
            cp_wait<0>();
        }
        __syncthreads();
        __half* As = (__half*)(smem_raw + buf * G3_STAGE);
        __half* Bs = (__half*)(smem_raw + buf * G3_STAGE + G3_AS);
#pragma unroll
        for (int kk = 0; kk < 4; kk++) {
            wmma::fragment<wmma::matrix_a, 16, 16, 16, __half, wmma::row_major> af[4];
#pragma unroll
            for (int i = 0; i < 4; i++)
                wmma::load_matrix_sync(af[i], As + (wr * 64 + i * 16) * 72 + kk * 16, 72);
#pragma unroll
            for (int j = 0; j < 4; j++) {
                wmma::fragment<wmma::matrix_b, 16, 16, 16, __half, wmma::row_major> bf;
                wmma::load_matrix_sync(bf, Bs + (kk * 16) * 136 + wc * 64 + j * 16, 136);
#pragma unroll
                for (int i = 0; i < 4; i++)
                    wmma::mma_sync(acc[i][j], af[i], bf, acc[i][j]);
            }
        }
        __syncthreads();
    }

    float* Cs = (float*)smem_raw;
#pragma unroll
    for (int i = 0; i < 4; i++)
#pragma unroll
        for (int j = 0; j < 4; j++)
            wmma::store_matrix_sync(Cs + (wr * 64 + i * 16) * 136 + wc * 64 + j * 16,
                                    acc[i][j], 136, wmma::mem_row_major);
    __syncthreads();
#pragma unroll 4
    for (int i = 0; i < 64; i++) {
        int e0 = (tid + (i << 7)) << 1;
        int r = e0 >> 7, c = e0 & 127;
        float v0 = Cs[r * 136 + c]     + bias[n0 + c];
        float v1 = Cs[r * 136 + c + 1] + bias[n0 + c + 1];
        const int gr = m0 + r, gc = n0 + c;
        if (mode == 0) {
            *(__half2*)((__half*)Cv + (size_t)gr * N + gc) = __floats2half2_rn(v0, v1);
        } else if (mode == 1) {
            *(__half2*)((__half*)Cv + (size_t)gr * N + gc) =
                __floats2half2_rn(gelu_f(v0), gelu_f(v1));
        } else if (mode == 2) {
            float* out = (float*)Cv;
            const float2 xv = *(const float2*)(xres + (size_t)gr * 3072 + gc);
            float2 o;
            o.x = xv.x + v0 * g_mod[6144 + gc];
            o.y = xv.y + v1 * g_mod[6144 + gc + 1];
            *(float2*)(out + (size_t)gr * 3072 + gc) = o;
        } else {
            if (n0 < QKVW_) {
                *(__half2*)((__half*)Cv + (size_t)gr * QKVW_ + gc) = __floats2half2_rn(v0, v1);
            } else if (gr < 2048 || gr >= 2560) {
                const int cr = gr < 2048 ? gr : gr - 512;
                *(__half2*)(g_cat + (size_t)cr * CATN_ + 3072 + (gc - QKVW_)) =
                    __floats2half2_rn(gelu_f(v0), gelu_f(v1));
            }
        }
    }
}

// ======================================================================
// QKV postprocess (unchanged, warp-per-head)
// ======================================================================
__global__ __launch_bounds__(768) void qkv_kernel(const float* __restrict__ fcos,
                                                  const float* __restrict__ fsin,
                                                  const float* __restrict__ qw,
                                                  const float* __restrict__ kw) {
    const int l    = blockIdx.x;
    const int hh   = threadIdx.x >> 5;
    const int lane = threadIdx.x & 31;
    const __half* hr = g_h + (size_t)l * QKVW_ + hh * 128 + lane * 4;

    uint2 qa = *(const uint2*)hr;
    uint2 ka = *(const uint2*)(hr + 3072);
    uint2 va = *(const uint2*)(hr + 6144);
    __half2 qh0 = *(__half2*)&qa.x, qh1 = *(__half2*)&qa.y;
    __half2 kh0 = *(__half2*)&ka.x, kh1 = *(__half2*)&ka.y;
    float q0 = __half2float(__low2half(qh0)), q1 = __half2float(__high2half(qh0));
    float q2 = __half2float(__low2half(qh1)), q3 = __half2float(__high2half(qh1));
    float k0 = __half2float(__low2half(kh0)), k1 = __half2float(__high2half(kh0));
    float k2 = __half2float(__low2half(kh1)), k3 = __half2float(__high2half(kh1));

    float sq = q0 * q0 + q1 * q1 + q2 * q2 + q3 * q3;
    float sk = k0 * k0 + k1 * k1 + k2 * k2 + k3 * k3;
#pragma unroll
    for (int o = 16; o; o >>= 1) {
        sq += __shfl_xor_sync(0xffffffffu, sq, o);
        sk += __shfl_xor_sync(0xffffffffu, sk, o);
    }
    const float rq = rsqrtf(sq * (1.0f / 128.0f) + 1e-6f);
    const float rk = rsqrtf(sk * (1.0f / 128.0f) + 1e-6f);
    const float4 wq = *(const float4*)(qw + lane * 4);
    const float4 wk = *(const float4*)(kw + lane * 4);
    q0 *= rq * wq.x; q1 *= rq * wq.y; q2 *= rq * wq.z; q3 *= rq * wq.w;
    k0 *= rk * wk.x; k1 *= rk * wk.y; k2 *= rk * wk.z; k3 *= rk * wk.w;

    if (l < IMG_) {
        const int p = lane * 2;
        const float c0 = fcos[l * 64 + p],     s0 = fsin[l * 64 + p];
        const float c1 = fcos[l * 64 + p + 1], s1 = fsin[l * 64 + p + 1];
        float t;
        t  = q0 * c0 - q1 * s0;  q1 = q0 * s0 + q1 * c0;  q0 = t;
        t  = q2 * c1 - q3 * s1;  q3 = q2 * s1 + q3 * c1;  q2 = t;
        t  = k0 * c0 - k1 * s0;  k1 = k0 * s0 + k1 * c0;  k0 = t;
        t  = k2 * c1 - k3 * s1;  k3 = k2 * s1 + k3 * c1;  k2 = t;
    }
    const size_t base = ((size_t)hh * L_ + l) * 128 + lane * 4;
    __half2 o0 = __floats2half2_rn(q0, q1), o1 = __floats2half2_rn(q2, q3);
    uint2 pk;
    pk.x = *(uint32_t*)&o0; pk.y = *(uint32_t*)&o1;
    *(uint2*)(g_q + base) = pk;
    o0 = __floats2half2_rn(k0, k1); o1 = __floats2half2_rn(k2, k3);
    pk.x = *(uint32_t*)&o0; pk.y = *(uint32_t*)&o1;
    *(uint2*)(g_k + base) = pk;
    *(uint2*)(g_v + base) = va;
}

// ======================================================================
// Flash attention v3 (FA2-style): raw mma.m16n8k16, register-resident
// Q / S / O / m / l.  128-query tile, 8 warps x 16 rows, kb=64 keys.
// One __syncthreads per k-block.  smem: Qs + K/V double buffers only.
//
// m16n8k16 layouts (PTX ISA): g = lane>>2, t = lane&3.
//  A(f16,row): a0={A[g][2t],A[g][2t+1]} a1={A[g+8][..]} a2={A[g][2t+8]..} a3={A[g+8][2t+8]..}
//  B(f16,col): b0={B[2t][g],B[2t+1][g]} b1={B[2t+8][g],B[2t+9][g]}
//  C(f32):     c0,c1=row g cols 2t,2t+1; c2,c3=row g+8 same cols
// ======================================================================
static constexpr int FLASH_SMEM_BYTES = 34816 + 4 * 17408;  // Qs + K/V x2 = 104448

__global__ __launch_bounds__(256) void flash_kernel() {
    extern __shared__ __align__(16) char smem_raw[];
    __half* Qs = (__half*)smem_raw;                                   // 128 x 136
    __half* Ksb[2] = { (__half*)(smem_raw + 34816), (__half*)(smem_raw + 52224) };
    __half* Vsb[2] = { (__half*)(smem_raw + 69632), (__half*)(smem_raw + 87040) };

    const int hh = blockIdx.y;
    const int bq = blockIdx.x;              // 0..17
    const int qt = bq < 16 ? bq : bq + 4;   // skip ref-query tiles
    const int t = threadIdx.x;
    const int w = t >> 5;                   // warp 0..7 -> q rows w*16..
    const int lane = t & 31;
    const int g  = lane >> 2;
    const int tq = lane & 3;

    auto stageKV = [&](int kb, int buf) {
        const __half* Kg = g_k + ((size_t)hh * L_ + kb * 64) * 128;
        const __half* Vg = g_v + ((size_t)hh * L_ + kb * 64) * 128;
        __half* Kd = Ksb[buf];
        __half* Vd = Vsb[buf];
#pragma unroll
        for (int i = 0; i < 4; i++) {
            int idx = t + (i << 8);
            int r = idx >> 4, c8 = (idx & 15) << 3;
            cp_async16(Kd + r * 136 + c8, Kg + r * 128 + c8);
            cp_async16(Vd + r * 136 + c8, Vg + r * 128 + c8);
        }
    };

    // stage Q to smem, then ldmatrix into registers (held whole kernel)
    const __half* Qg = g_q + ((size_t)hh * L_ + qt * 128) * 128;
#pragma unroll
    for (int i = 0; i < 8; i++) {
        int idx = t + (i << 8);
        int r = idx >> 4, c8 = (idx & 15) << 3;
        *(uint4*)(Qs + r * 136 + c8) = *(const uint4*)(Qg + r * 128 + c8);
    }
    __syncthreads();

    uint32_t qa[8][4];
    {
        const int qrow = w * 16 + ((lane >> 3) & 1) * 8 + (lane & 7);
        const int qcol = (lane >> 4) * 8;
#pragma unroll
        for (int kk = 0; kk < 8; kk++) {
            uint32_t addr = (uint32_t)__cvta_generic_to_shared(
                Qs + qrow * 136 + kk * 16 + qcol);
            ldsm_x4(qa[kk][0], qa[kk][1], qa[kk][2], qa[kk][3], addr);
        }
    }

    float oacc[16][4];
#pragma unroll
    for (int j = 0; j < 16; j++)
#pragma unroll
        for (int e = 0; e < 4; e++) oacc[j][e] = 0.0f;
    float m0 = -1e30f, m1 = -1e30f, l0 = 0.0f, l1 = 0.0f;

    // K-ldmatrix lane geometry (no trans): row within 16-row pair, col half
    const int krow = ((lane >> 4) & 1) * 8 + (lane & 7);
    const int kcol = ((lane >> 3) & 1) * 8;
    // V-ldmatrix (trans): k-row and n-col halves
    const int vrow = ((lane >> 3) & 1) * 8 + (lane & 7);
    const int vcol = ((lane >> 4) & 1) * 8;

    stageKV(0, 0); cp_commit();

    for (int kb = 0; kb < 44; kb++) {
        const int buf = kb & 1;
        cp_wait<0>();
        __syncthreads();   // staged data visible; all warps done with buf^1 reads
        if (kb + 1 < 44) { stageKV(kb + 1, buf ^ 1); cp_commit(); }
        __half* Ks = Ksb[buf];
        __half* Vs = Vsb[buf];

        // ---- S = Q @ K^T (16 x 64 per warp), reg accumulators ----
        float sacc[8][4];
#pragma unroll
        for (int j = 0; j < 8; j++)
#pragma unroll
            for (int e = 0; e < 4; e++) sacc[j][e] = 0.0f;
#pragma unroll
        for (int kk = 0; kk < 8; kk++) {
#pragma unroll
            for (int jp = 0; jp < 4; jp++) {
                uint32_t b0, b1, b2, b3;
                uint32_t addr = (uint32_t)__cvta_generic_to_shared(
                    Ks + (jp * 16 + krow) * 136 + kk * 16 + kcol);
                ldsm_x4(b0, b1, b2, b3, addr);
                mma16816(sacc[2 * jp],     qa[kk], b0, b1);
                mma16816(sacc[2 * jp + 1], qa[kk], b2, b3);
            }
        }

        // ---- softmax on registers (rows g, g+8 of this warp's 16) ----
        const float scl = 0.088388347648318447f;   // 1/sqrt(128)
        float mx0 = -1e30f, mx1 = -1e30f;
#pragma unroll
        for (int j = 0; j < 8; j++) {
            sacc[j][0] *= scl; sacc[j][1] *= scl;
            sacc[j][2] *= scl; sacc[j][3] *= scl;
            mx0 = fmaxf(mx0, fmaxf(sacc[j][0], sacc[j][1]));
            mx1 = fmaxf(mx1, fmaxf(sacc[j][2], sacc[j][3]));
        }
        mx0 = fmaxf(mx0, __shfl_xor_sync(0xffffffffu, mx0, 1));
        mx0 = fmaxf(mx0, __shfl_xor_sync(0xffffffffu, mx0, 2));
        mx1 = fmaxf(mx1, __shfl_xor_sync(0xffffffffu, mx1, 1));
        mx1 = fmaxf(mx1, __shfl_xor_sync(0xffffffffu, mx1, 2));
        const float mn0 = fmaxf(m0, mx0);
        const float mn1 = fmaxf(m1, mx1);
        const float al0 = __expf(m0 - mn0);
        const float al1 = __expf(m1 - mn1);

        uint32_t pa[4][4];
        float sum0 = 0.0f, sum1 = 0.0f;
#pragma unroll
        for (int kv = 0; kv < 4; kv++) {
            float p00 = __expf(sacc[2 * kv][0] - mn0);
            float p01 = __expf(sacc[2 * kv][1] - mn0);
            float p02 = __expf(sacc[2 * kv][2] - mn1);
            float p03 = __expf(sacc[2 * kv][3] - mn1);
            float p10 = __expf(sacc[2 * kv + 1][0] - mn0);
            float p11 = __expf(sacc[2 * kv + 1][1] - mn0);
            float p12 = __expf(sacc[2 * kv + 1][2] - mn1);
            float p13 = __expf(sacc[2 * kv + 1][3] - mn1);
            sum0 += p00 + p01 + p10 + p11;
            sum1 += p02 + p03 + p12 + p13;
            __half2 h;
            h = __floats2half2_rn(p00, p01); pa[kv][0] = *(uint32_t*)&h;
            h = __floats2half2_rn(p02, p03); pa[kv][1] = *(uint32_t*)&h;
            h = __floats2half2_rn(p10, p11); pa[kv][2] = *(uint32_t*)&h;
            h = __floats2half2_rn(p12, p13); pa[kv][3] = *(uint32_t*)&h;
        }
        sum0 += __shfl_xor_sync(0xffffffffu, sum0, 1);
        sum0 += __shfl_xor_sync(0xffffffffu, sum0, 2);
        sum1 += __shfl_xor_sync(0xffffffffu, sum1, 1);
        sum1 += __shfl_xor_sync(0xffffffffu, sum1, 2);
        l0 = l0 * al0 + sum0;
        l1 = l1 * al1 + sum1;
        m0 = mn0; m1 = mn1;

        // ---- rescale O in registers ----
#pragma unroll
        for (int j = 0; j < 16; j++) {
            oacc[j][0] *= al0; oacc[j][1] *= al0;
            oacc[j][2] *= al1; oacc[j][3] *= al1;
        }
        // ---- O += P @ V (16 x 128 per warp) ----
#pragma unroll
        for (int kv = 0; kv < 4; kv++) {
#pragma unroll
            for (int np = 0; np < 8; np++) {
                uint32_t b0, b1, b2, b3;
                uint32_t addr = (uint32_t)__cvta_generic_to_shared(
                    Vs + (kv * 16 + vrow) * 136 + np * 16 + vcol);
                ldsm_x4_trans(b0, b1, b2, b3, addr);
                mma16816(oacc[2 * np],     pa[kv], b0, b1);
                mma16816(oacc[2 * np + 1], pa[kv], b2, b3);
            }
        }
    }

    // ---- finalize: normalize by l, write half2 to g_cat (ref rows dropped) ----
    const int r0 = qt * 128 + w * 16 + g;
    const int r1 = r0 + 8;
    const int cr0 = r0 < IMG_ ? r0 : r0 - 512;
    const int cr1 = r1 < IMG_ ? r1 : r1 - 512;
    const float il0 = 1.0f / l0, il1 = 1.0f / l1;
#pragma unroll
    for (int j = 0; j < 16; j++) {
        const int col = hh * 128 + j * 8 + tq * 2;
        *(__half2*)(g_cat + (size_t)cr0 * CATN_ + col) =
            __floats2half2_rn(oacc[j][0] * il0, oacc[j][1] * il0);
        *(__half2*)(g_cat + (size_t)cr1 * CATN_ + col) =
            __floats2half2_rn(oacc[j][2] * il1, oacc[j][3] * il1);
    }
}

// ======================================================================
// host launcher  (GEMM kept at launch slot 4 for the ncu capture window)
// ======================================================================
extern "C" void kernel_launch(void* const* d_in, const int* in_sizes, int n_in,
                              void* d_out, int out_size) {
    const float* x    = (const float*)d_in[0];
    const float* vec  = (const float*)d_in[1];
    const float* ref  = (const float*)d_in[2];
    const float* fcos = (const float*)d_in[3];
    const float* fsin = (const float*)d_in[4];
    const float* modw = (const float*)d_in[5];
    const float* modb = (const float*)d_in[6];
    const float* rf1w = (const float*)d_in[7];
    const float* rf1b = (const float*)d_in[8];
    const float* rf2w = (const float*)d_in[9];
    const float* rf2b = (const float*)d_in[10];
    const float* rnw  = (const float*)d_in[11];
    const float* rnb  = (const float*)d_in[12];
    const float* l1w  = (const float*)d_in[13];
    const float* l1b  = (const float*)d_in[14];
    const float* l2w  = (const float*)d_in[15];
    const float* l2b  = (const float*)d_in[16];
    const float* qw   = (const float*)d_in[17];
    const float* kw   = (const float*)d_in[18];
    float* out = (float*)d_out;
    (void)in_sizes; (void)n_in; (void)out_size;

    cudaFuncSetAttribute(gemm_h, cudaFuncAttributeMaxDynamicSharedMemorySize, GEMM_SMEM_BYTES);
    cudaFuncSetAttribute(flash_kernel, cudaFuncAttributeMaxDynamicSharedMemorySize, FLASH_SMEM_BYTES);

    __half *xm_p, *refc_p, *rtmp_p, *h_p, *cat_p, *w1h_p, *w2h_p, *wr1h_p, *wr2h_p;
    cudaGetSymbolAddress((void**)&xm_p,   g_xm);
    cudaGetSymbolAddress((void**)&refc_p, g_refc);
    cudaGetSymbolAddress((void**)&rtmp_p, g_rtmp);
    cudaGetSymbolAddress((void**)&h_p,    g_h);
    cudaGetSymbolAddress((void**)&cat_p,  g_cat);
    cudaGetSymbolAddress((void**)&w1h_p,  g_w1h);
    cudaGetSymbolAddress((void**)&w2h_p,  g_w2h);
    cudaGetSymbolAddress((void**)&wr1h_p, g_wr1h);
    cudaGetSymbolAddress((void**)&wr2h_p, g_wr2h);

    refcopy_kernel<<<512 * 3072 / 1024, 256>>>(ref);
    h_convert<<<D_ * D_ / 2048, 256>>>(rf1w, wr1h_p);
    h_convert<<<D_ * D_ / 2048, 256>>>(rf2w, wr2h_p);
    gemm_h<<<4 * 24, 128, GEMM_SMEM_BYTES>>>(refc_p, wr1h_p, rf1b, rtmp_p,
                                             D_, D_, 4, 24, 1, nullptr);
    mod_part_kernel<<<dim3(36, 12), 256>>>(vec, modw);
    mod_reduce_kernel<<<36, 256>>>(modb);
    xmod_kernel<<<LX_, 256>>>(x);
    gemm_h<<<4 * 24, 128, GEMM_SMEM_BYTES>>>(rtmp_p, wr2h_p, rf2b,
                                             xm_p + (size_t)2048 * D_,
                                             D_, D_, 4, 24, 0, nullptr);
    refln_kernel<<<512, 256>>>(rnw, rnb);
    h_convert<<<(int)((size_t)D_ * NOUT_ / 2048), 256>>>(l1w, w1h_p);
    gemm_h<<<22 * 168, 128, GEMM_SMEM_BYTES>>>(xm_p, w1h_p, l1b, h_p,
                                               NOUT_, D_, 22, 168, 3, nullptr);
    qkv_kernel<<<L_, 768>>>(fcos, fsin, qw, kw);
    h_convert<<<(int)((size_t)CATN_ * D_ / 2048), 256>>>(l2w, w2h_p);
    flash_kernel<<<dim3(18, 24), 256, FLASH_SMEM_BYTES>>>();
    gemm_h<<<18 * 24, 128, GEMM_SMEM_BYTES>>>(cat_p, w2h_p, l2b, out,
                                              D_, CATN_, 18, 24, 2, x);
}